// round 14
// baseline (speedup 1.0000x reference)
#include <cuda_runtime.h>
#include <cuda_fp16.h>
#include <math.h>
#include <stdint.h>

// ---------------------------------------------------------------------------
// TimeSformer block, sm_103 legacy-mma path. Round 13:
//   * hgemm_big: 4-stage x 32-K cp.async ring with wait_group(2) — one extra
//     stage of slack hides the per-iteration arrival latency; registers
//     unchanged vs R12 (the spill variable that killed R11).
//   * attention kernels + everything else unchanged from R12 (823.3us).
// ---------------------------------------------------------------------------

#define FRAMES_C  256
#define PATCHES_C 64
#define DIM_C     512
#define HEADS_C   8
#define DH_C      64
#define DFF_C     1024
#define KLIN_C    128
#define NT_T      257
#define NT_S      65
#define BT_C      64
#define BS_C      256
#define ETLD      80
#define SFLD_T    276
#define SFLD_S    132

// ------------------------- scratch (device globals) ------------------------
__device__ __half hXT  [((size_t)BT_C * NT_T + 64) * DIM_C];
__device__ float  fXT  [(size_t)BT_C * NT_T * DIM_C];
__device__ __half hQKVT[((size_t)BT_C * NT_T + 16) * 3 * DIM_C];
__device__ __half hOT  [((size_t)BT_C * NT_T + 64) * DIM_C];
__device__ float  fY1  [(size_t)BT_C * NT_T * DIM_C];
__device__ __half hZ   [((size_t)BS_C * NT_S + 64) * DIM_C];
__device__ float  fZ   [(size_t)BS_C * NT_S * DIM_C];
__device__ __half hQKVS[((size_t)BS_C * NT_S + 16) * 3 * DIM_C];
__device__ __half hEt  [(size_t)KLIN_C * ETLD];
__device__ __half hKC  [(size_t)BS_C * HEADS_C * KLIN_C * DH_C];
__device__ __half hVC  [(size_t)BS_C * HEADS_C * KLIN_C * DH_C];
__device__ __half hOS  [((size_t)BS_C * NT_S + 64) * DIM_C];
__device__ float  fY2  [(size_t)BS_C * NT_S * DIM_C];
__device__ __half hY2  [((size_t)BS_C * NT_S + 64) * DIM_C];
__device__ __half hH   [((size_t)BS_C * NT_S + 64) * DFF_C];
__device__ __half tWqkv_t[(size_t)3 * DIM_C * DIM_C];
__device__ __half tWo_t  [(size_t)DIM_C * DIM_C];
__device__ __half tWqkv_s[(size_t)3 * DIM_C * DIM_C];
__device__ __half tWo_s  [(size_t)DIM_C * DIM_C];
__device__ __half tW1    [(size_t)DFF_C * DIM_C];
__device__ __half tW2    [(size_t)DIM_C * DFF_C];

// ------------------------------ helpers -------------------------------------
__device__ __forceinline__ uint32_t smaddr(const void* p) {
    uint32_t a;
    asm("{ .reg .u64 t; cvta.to.shared.u64 t, %1; cvt.u32.u64 %0, t; }" : "=r"(a) : "l"(p));
    return a;
}
__device__ __forceinline__ void ldmx4(uint32_t& r0, uint32_t& r1, uint32_t& r2, uint32_t& r3,
                                      uint32_t a) {
    asm volatile("ldmatrix.sync.aligned.m8n8.x4.shared.b16 {%0,%1,%2,%3}, [%4];"
                 : "=r"(r0), "=r"(r1), "=r"(r2), "=r"(r3) : "r"(a));
}
__device__ __forceinline__ void ldmx4t(uint32_t& r0, uint32_t& r1, uint32_t& r2, uint32_t& r3,
                                       uint32_t a) {
    asm volatile("ldmatrix.sync.aligned.m8n8.x4.trans.shared.b16 {%0,%1,%2,%3}, [%4];"
                 : "=r"(r0), "=r"(r1), "=r"(r2), "=r"(r3) : "r"(a));
}
__device__ __forceinline__ void mma16816(float c[4], const uint32_t a[4], const uint32_t b[2]) {
    asm volatile("mma.sync.aligned.m16n8k16.row.col.f32.f16.f16.f32 "
                 "{%0,%1,%2,%3},{%4,%5,%6,%7},{%8,%9},{%0,%1,%2,%3};"
                 : "+f"(c[0]), "+f"(c[1]), "+f"(c[2]), "+f"(c[3])
                 : "r"(a[0]), "r"(a[1]), "r"(a[2]), "r"(a[3]), "r"(b[0]), "r"(b[1]));
}
#define CPA16(dst, src) \
    asm volatile("cp.async.cg.shared.global [%0], [%1], 16;" :: "r"(dst), "l"(src) : "memory")
#define CPA_COMMIT() asm volatile("cp.async.commit_group;" ::: "memory")
#define CPA_WAIT(n)  asm volatile("cp.async.wait_group %0;" :: "n"(n) : "memory")

// ------------------------------- prep kernels -------------------------------
__global__ void prep_weights(const float* __restrict__ Wqkv_t, const float* __restrict__ Wo_t,
                             const float* __restrict__ Wqkv_s, const float* __restrict__ Wo_s,
                             const float* __restrict__ W1, const float* __restrict__ W2) {
    long i = (long)blockIdx.x * 256 + threadIdx.x;
    const long n1 = 786432, n2 = n1 + 262144, n3 = n2 + 786432,
               n4 = n3 + 262144, n5 = n4 + 524288, n6 = n5 + 524288;
    const float* src; __half* dst; long j; int K, N;
    if (i < n1)      { src = Wqkv_t; dst = tWqkv_t; j = i;      K = 512;  N = 1536; }
    else if (i < n2) { src = Wo_t;   dst = tWo_t;   j = i - n1; K = 512;  N = 512;  }
    else if (i < n3) { src = Wqkv_s; dst = tWqkv_s; j = i - n2; K = 512;  N = 1536; }
    else if (i < n4) { src = Wo_s;   dst = tWo_s;   j = i - n3; K = 512;  N = 512;  }
    else if (i < n5) { src = W1;     dst = tW1;     j = i - n4; K = 512;  N = 1024; }
    else if (i < n6) { src = W2;     dst = tW2;     j = i - n5; K = 1024; N = 512;  }
    else return;
    int k = (int)(j % K), n = (int)(j / K);
    dst[j] = __float2half_rn(src[(long)k * N + n]);
}
__global__ void build_xt(const float* __restrict__ x) {
    long idx = (long)blockIdx.x * blockDim.x + threadIdx.x;
    const long total = (long)BT_C * NT_T * DIM_C;
    if (idx >= total) return;
    int d = (int)(idx % DIM_C);
    long r = idx / DIM_C;
    int t = (int)(r % NT_T);
    int p = (int)(r / NT_T);
    float v;
    if (t == 0) v = x[d];
    else        v = x[(long)(1 + (t - 1) * PATCHES_C + p) * DIM_C + d];
    hXT[idx] = __float2half_rn(v);
    fXT[idx] = v;
}
__global__ void build_z() {
    long idx = (long)blockIdx.x * blockDim.x + threadIdx.x;
    const long total = (long)BS_C * NT_S * DIM_C;
    if (idx >= total) return;
    int d = (int)(idx % DIM_C);
    long r = idx / DIM_C;
    int s = (int)(r % NT_S);
    int f = (int)(r / NT_S);
    float v;
    if (s == 0) v = fY1[(long)(f & 63) * NT_T * DIM_C + d];
    else        v = fY1[(long)(s - 1) * NT_T * DIM_C + (long)(1 + f) * DIM_C + d];
    hZ[idx] = __float2half_rn(v);
    fZ[idx] = v;
}
__global__ void transpose_E(const float* __restrict__ E) {
    int i = blockIdx.x * blockDim.x + threadIdx.x;
    if (i >= KLIN_C * NT_S) return;
    int j = i % NT_S, kc = i / NT_S;
    hEt[kc * ETLD + j] = __float2half_rn(E[j * KLIN_C + kc]);
}

// ========= fused temporal attention (257 keys, dh=64), 512 threads ==========
#define ATNT_SMEM (9216 + 9216 + 39168 + 64 * SFLD_T * 4)
__global__ void __launch_bounds__(512, 1)
attn_t() {
    extern __shared__ char sm[];
    __half* Qs = (__half*)sm;
    __half* Ks = (__half*)(sm + 9216);
    __half* Vs = (__half*)(sm + 18432);
    float*  SPf = (float*)(sm + 57600);
    const int tid = threadIdx.x, lane = tid & 31, warp = tid >> 5;
    const int bm = blockIdx.x * 64;
    const int b = blockIdx.y >> 3, h = blockIdx.y & 7;
    const __half* Qg = hQKVT + (size_t)b * NT_T * (3 * DIM_C) + h * 64;
    const __half* Kg = Qg + DIM_C;
    const __half* Vg = Qg + 2 * DIM_C;
    const float4 z4 = make_float4(0.f, 0.f, 0.f, 0.f);

    {
        int r = tid >> 3, s = tid & 7;
        int gr = bm + r;
        float4 v = (gr < NT_T) ? *(const float4*)(Qg + (size_t)gr * 1536 + s * 8) : z4;
        *(float4*)&Qs[r * 72 + s * 8] = v;
    }
    for (int i = tid; i < 2176; i += 512) {
        int r = i >> 3, s = i & 7;
        float4 v = (r < NT_T) ? *(const float4*)(Vg + (size_t)r * 1536 + s * 8) : z4;
        *(float4*)&Vs[r * 72 + s * 8] = v;
    }
    __syncthreads();

    const int wr = warp >> 2, wc = warp & 3;
    uint32_t aq[4][4];
    #pragma unroll
    for (int ks = 0; ks < 4; ks++) {
        uint32_t ad = smaddr(&Qs[(wr * 16 + (lane & 15)) * 72 +
                                 ks * 16 + ((lane & 16) ? 8 : 0)]);
        ldmx4(aq[ks][0], aq[ks][1], aq[ks][2], aq[ks][3], ad);
    }

    for (int kt = 0; kt < 5; kt++) {
        __syncthreads();
        {
            int r = tid >> 3, s = tid & 7;
            int key = kt * 64 + r;
            float4 v = (key < NT_T) ? *(const float4*)(Kg + (size_t)key * 1536 + s * 8) : z4;
            *(float4*)&Ks[r * 72 + s * 8] = v;
        }
        __syncthreads();
        float c[2][4];
        #pragma unroll
        for (int nt = 0; nt < 2; nt++)
            #pragma unroll
            for (int q = 0; q < 4; q++) c[nt][q] = 0.f;
        #pragma unroll
        for (int ks = 0; ks < 4; ks++) {
            uint32_t r0, r1, r2, r3;
            uint32_t bd = smaddr(&Ks[(wc * 16 + (lane & 7) + ((lane & 16) ? 8 : 0)) * 72 +
                                     ks * 16 + (lane & 8)]);
            ldmx4(r0, r1, r2, r3, bd);
            uint32_t bf0[2] = {r0, r1}, bf1[2] = {r2, r3};
            mma16816(c[0], aq[ks], bf0);
            mma16816(c[1], aq[ks], bf1);
        }
        #pragma unroll
        for (int nt = 0; nt < 2; nt++) {
            int row = wr * 16 + (lane >> 2);
            int col0 = kt * 64 + wc * 16 + nt * 8 + (lane & 3) * 2;
            #pragma unroll
            for (int h2 = 0; h2 < 2; h2++)
                #pragma unroll
                for (int j = 0; j < 2; j++) {
                    int col = col0 + j;
                    if (col < NT_T)
                        SPf[(row + h2 * 8) * SFLD_T + col] =
                            c[nt][h2 * 2 + j] * 0.125f;
                }
        }
    }
    __syncthreads();

    #pragma unroll 1
    for (int rr = 0; rr < 4; rr++) {
        int row = warp * 4 + rr;
        float* sp = &SPf[row * SFLD_T];
        __half* hp = (__half*)sp;
        float v[9];
        float m = -1e30f;
        #pragma unroll
        for (int i2 = 0; i2 < 9; i2++) {
            int cc = lane + i2 * 32;
            v[i2] = (cc < NT_T) ? sp[cc] : -1e30f;
            m = fmaxf(m, v[i2]);
        }
        #pragma unroll
        for (int s = 16; s > 0; s >>= 1) m = fmaxf(m, __shfl_xor_sync(0xffffffffu, m, s));
        float sum = 0.f;
        #pragma unroll
        for (int i2 = 0; i2 < 9; i2++) {
            int cc = lane + i2 * 32;
            if (cc < NT_T) { v[i2] = __expf(v[i2] - m); sum += v[i2]; }
        }
        #pragma unroll
        for (int s = 16; s > 0; s >>= 1) sum += __shfl_xor_sync(0xffffffffu, sum, s);
        float inv = 1.f / sum;
        __syncwarp();
        #pragma unroll
        for (int i2 = 0; i2 < 9; i2++) {
            int cc = lane + i2 * 32;
            if (cc < NT_T) hp[cc] = __float2half_rn(v[i2] * inv);
        }
        for (int cc = NT_T + lane; cc < 272; cc += 32) hp[cc] = __float2half_rn(0.f);
    }
    __syncthreads();

    float o[2][4];
    #pragma unroll
    for (int nt = 0; nt < 2; nt++)
        #pragma unroll
        for (int q = 0; q < 4; q++) o[nt][q] = 0.f;
    __half* Ph = (__half*)SPf;
    const int PLD = SFLD_T * 2;
    #pragma unroll 1
    for (int ks = 0; ks < 17; ks++) {
        uint32_t ap[4];
        uint32_t ad = smaddr(&Ph[(wr * 16 + (lane & 15)) * PLD +
                                 ks * 16 + ((lane & 16) ? 8 : 0)]);
        ldmx4(ap[0], ap[1], ap[2], ap[3], ad);
        uint32_t r0, r1, r2, r3;
        uint32_t bd = smaddr(&Vs[(ks * 16 + (lane & 15)) * 72 +
                                 wc * 16 + ((lane & 16) ? 8 : 0)]);
        ldmx4t(r0, r1, r2, r3, bd);
        uint32_t bf0[2] = {r0, r1}, bf1[2] = {r2, r3};
        mma16816(o[0], ap, bf0);
        mma16816(o[1], ap, bf1);
    }
    #pragma unroll
    for (int nt = 0; nt < 2; nt++) {
        int row0 = bm + wr * 16 + (lane >> 2);
        int col0 = h * 64 + wc * 16 + nt * 8 + (lane & 3) * 2;
        #pragma unroll
        for (int h2 = 0; h2 < 2; h2++) {
            int row = row0 + h2 * 8;
            if (row >= NT_T) continue;
            #pragma unroll
            for (int j = 0; j < 2; j++)
                hOT[((size_t)b * NT_T + row) * 512 + col0 + j] =
                    __float2half_rn(o[nt][h2 * 2 + j]);
        }
    }
}

// ===== fused spatial Linformer attention (128 keys), 320 threads ============
#define ATNS_SMEM (11520 + 18432 + 18432 + 80 * SFLD_S * 4)
__global__ void __launch_bounds__(320, 2)
attn_s() {
    extern __shared__ char sm[];
    __half* Qs = (__half*)sm;
    __half* Ks = (__half*)(sm + 11520);
    __half* Vs = (__half*)(sm + 29952);
    float*  SPf = (float*)(sm + 48384);
    const int tid = threadIdx.x, lane = tid & 31, warp = tid >> 5;
    const int f = blockIdx.x >> 3, h = blockIdx.x & 7;
    const __half* Qg = hQKVS + (size_t)f * NT_S * (3 * DIM_C) + h * 64;
    const __half* Kc = hKC + (size_t)blockIdx.x * (KLIN_C * DH_C);
    const __half* Vc = hVC + (size_t)blockIdx.x * (KLIN_C * DH_C);
    const float4 z4 = make_float4(0.f, 0.f, 0.f, 0.f);

    for (int i = tid; i < 640; i += 320) {
        int r = i >> 3, s = i & 7;
        float4 v = (r < NT_S) ? *(const float4*)(Qg + (size_t)r * 1536 + s * 8) : z4;
        *(float4*)&Qs[r * 72 + s * 8] = v;
    }
    for (int i = tid; i < 1024; i += 320) {
        int r = i >> 3, s = i & 7;
        *(float4*)&Ks[r * 72 + s * 8] = *(const float4*)(Kc + (size_t)r * 64 + s * 8);
    }
    for (int i = tid; i < 1024; i += 320) {
        int r = i >> 3, s = i & 7;
        *(float4*)&Vs[r * 72 + s * 8] = *(const float4*)(Vc + (size_t)r * 64 + s * 8);
    }
    __syncthreads();

    const int wr = warp >> 1, wc = warp & 1;
    uint32_t aq[4][4];
    #pragma unroll
    for (int ks = 0; ks < 4; ks++) {
        uint32_t ad = smaddr(&Qs[(wr * 16 + (lane & 15)) * 72 +
                                 ks * 16 + ((lane & 16) ? 8 : 0)]);
        ldmx4(aq[ks][0], aq[ks][1], aq[ks][2], aq[ks][3], ad);
    }
    float c[8][4];
    #pragma unroll
    for (int nt = 0; nt < 8; nt++)
        #pragma unroll
        for (int q = 0; q < 4; q++) c[nt][q] = 0.f;
    #pragma unroll
    for (int ks = 0; ks < 4; ks++)
        #pragma unroll
        for (int p = 0; p < 4; p++) {
            uint32_t r0, r1, r2, r3;
            uint32_t bd = smaddr(&Ks[(wc * 64 + p * 16 + (lane & 7) +
                                      ((lane & 16) ? 8 : 0)) * 72 +
                                     ks * 16 + (lane & 8)]);
            ldmx4(r0, r1, r2, r3, bd);
            uint32_t bf0[2] = {r0, r1}, bf1[2] = {r2, r3};
            mma16816(c[2 * p], aq[ks], bf0);
            mma16816(c[2 * p + 1], aq[ks], bf1);
        }
    #pragma unroll
    for (int nt = 0; nt < 8; nt++) {
        int row = wr * 16 + (lane >> 2);
        int col0 = wc * 64 + (nt >> 1) * 16 + (nt & 1) * 8 + (lane & 3) * 2;
        #pragma unroll
        for (int h2 = 0; h2 < 2; h2++)
            #pragma unroll
            for (int j = 0; j < 2; j++)
                SPf[(row + h2 * 8) * SFLD_S + col0 + j] =
                    c[nt][h2 * 2 + j] * 0.125f;
    }
    __syncthreads();

    #pragma unroll 1
    for (int rr = 0; rr < 8; rr++) {
        int row = warp * 8 + rr;
        float* sp = &SPf[row * SFLD_S];
        __half* hp = (__half*)sp;
        if (row < NT_S) {
            float v[4];
            float m = -1e30f;
            #pragma unroll
            for (int i2 = 0; i2 < 4; i2++) {
                v[i2] = sp[lane + i2 * 32];
                m = fmaxf(m, v[i2]);
            }
            #pragma unroll
            for (int s = 16; s > 0; s >>= 1) m = fmaxf(m, __shfl_xor_sync(0xffffffffu, m, s));
            float sum = 0.f;
            #pragma unroll
            for (int i2 = 0; i2 < 4; i2++) { v[i2] = __expf(v[i2] - m); sum += v[i2]; }
            #pragma unroll
            for (int s = 16; s > 0; s >>= 1) sum += __shfl_xor_sync(0xffffffffu, sum, s);
            float inv = 1.f / sum;
            __syncwarp();
            #pragma unroll
            for (int i2 = 0; i2 < 4; i2++)
                hp[lane + i2 * 32] = __float2half_rn(v[i2] * inv);
        } else {
            #pragma unroll
            for (int i2 = 0; i2 < 4; i2++) hp[lane + i2 * 32] = __float2half_rn(0.f);
        }
    }
    __syncthreads();

    float o[4][4];
    #pragma unroll
    for (int nt = 0; nt < 4; nt++)
        #pragma unroll
        for (int q = 0; q < 4; q++) o[nt][q] = 0.f;
    __half* Ph = (__half*)SPf;
    const int PLD = SFLD_S * 2;
    #pragma unroll 1
    for (int ks = 0; ks < 8; ks++) {
        uint32_t ap[4];
        uint32_t ad = smaddr(&Ph[(wr * 16 + (lane & 15)) * PLD +
                                 ks * 16 + ((lane & 16) ? 8 : 0)]);
        ldmx4(ap[0], ap[1], ap[2], ap[3], ad);
        #pragma unroll
        for (int p = 0; p < 2; p++) {
            uint32_t r0, r1, r2, r3;
            uint32_t bd = smaddr(&Vs[(ks * 16 + (lane & 15)) * 72 +
                                     wc * 32 + p * 16 + ((lane & 16) ? 8 : 0)]);
            ldmx4t(r0, r1, r2, r3, bd);
            uint32_t bf0[2] = {r0, r1}, bf1[2] = {r2, r3};
            mma16816(o[2 * p], ap, bf0);
            mma16816(o[2 * p + 1], ap, bf1);
        }
    }
    #pragma unroll
    for (int nt = 0; nt < 4; nt++) {
        int row0 = wr * 16 + (lane >> 2);
        int col0 = h * 64 + wc * 32 + (nt >> 1) * 16 + (nt & 1) * 8 + (lane & 3) * 2;
        #pragma unroll
        for (int h2 = 0; h2 < 2; h2++) {
            int row = row0 + h2 * 8;
            if (row >= NT_S) continue;
            #pragma unroll
            for (int j = 0; j < 2; j++)
                hOS[((size_t)f * NT_S + row) * 512 + col0 + j] =
                    __float2half_rn(o[nt][h2 * 2 + j]);
        }
    }
}

// ====== big fp16 GEMM, 4-stage x 32-K cp.async, wait_group(2) ==============
#define HGB_STAGE 20480
#define HGB_SMEM  (4 * HGB_STAGE)

template<int EPI, int OUT>
__global__ void __launch_bounds__(256, 2)
hgemm_big(const __half* __restrict__ A, const __half* __restrict__ Bt,
          __half* __restrict__ Ch, float* __restrict__ Cf,
          const float* __restrict__ bias, const float* __restrict__ Rf,
          int M, int N, int K, int ldc)
{
    constexpr int BK = 32;
    extern __shared__ char smraw[];
    const uint32_t sb = smaddr(smraw);

    const int tid = threadIdx.x, lane = tid & 31, warp = tid >> 5;
    const int wr = warp >> 2, wc = warp & 3;
    const int bm = blockIdx.y * 128, bn = blockIdx.x * 128;
    A  += (long)bm * K;
    Bt += (long)bn * K;

    float c[4][4][4];
    #pragma unroll
    for (int i = 0; i < 4; i++)
        #pragma unroll
        for (int j = 0; j < 4; j++)
            #pragma unroll
            for (int q = 0; q < 4; q++) c[i][j][q] = 0.f;

    auto prefetch = [&](int t) {
        int s = t & 3;
        uint32_t ab = sb + s * HGB_STAGE;
        uint32_t bb = ab + 10240;
        int k0 = t * BK;
        #pragma unroll
        for (int i = 0; i < 2; i++) {
            int ch = tid + i * 256;
            int row = ch >> 2, seg = ch & 3;
            CPA16(ab + row * 80 + seg * 16, A + (long)row * K + k0 + seg * 8);
            CPA16(bb + row * 80 + seg * 16, Bt + (long)row * K + k0 + seg * 8);
        }
        CPA_COMMIT();
    };

    auto comp = [&](int s) {
        const __half* Asb = (const __half*)(smraw + s * HGB_STAGE);
        const __half* Bsb = (const __half*)(smraw + s * HGB_STAGE + 10240);
        #pragma unroll
        for (int ks = 0; ks < 2; ks++) {
            int k0 = ks * 16;
            uint32_t af[4][4], bf[4][2];
            #pragma unroll
            for (int mt = 0; mt < 4; mt++) {
                uint32_t ad = smaddr(Asb + (wr * 64 + mt * 16 + (lane & 15)) * 40 +
                                     k0 + ((lane & 16) ? 8 : 0));
                ldmx4(af[mt][0], af[mt][1], af[mt][2], af[mt][3], ad);
            }
            #pragma unroll
            for (int p = 0; p < 2; p++) {
                int n0 = wc * 32 + p * 16;
                uint32_t bd = smaddr(Bsb + (n0 + (lane & 7) + ((lane & 16) ? 8 : 0)) * 40 +
                                     k0 + (lane & 8));
                uint32_t r0, r1, r2, r3;
                ldmx4(r0, r1, r2, r3, bd);
                bf[2 * p][0] = r0; bf[2 * p][1] = r1;
                bf[2 * p + 1][0] = r2; bf[2 * p + 1][1] = r3;
            }
            #pragma unroll
            for (int mt = 0; mt < 4; mt++)
                #pragma unroll
                for (int nt = 0; nt < 4; nt++)
                    mma16816(c[mt][nt], af[mt], bf[nt]);
        }
    };

    const int ntl = K / BK;    // >= 16
    prefetch(0);
    prefetch(1);
    prefetch(2);
    CPA_WAIT(2);
    __syncthreads();
    for (int t = 0; t < ntl; t++) {
        comp(t & 3);
        if (t + 3 < ntl) {
            prefetch(t + 3);
            CPA_WAIT(2);
        } else {
            int r = ntl - 1 - t;
            if (r >= 2)      CPA_WAIT(1);
            else if (r == 1) CPA_WAIT(0);
        }
        __syncthreads();
    }

    #pragma unroll
    for (int mt = 0; mt < 4; mt++) {
        #pragma unroll
        for (int nt = 0; nt < 4; nt++) {
            int r0 = bm + wr * 64 + mt * 16 + (lane >> 2);
            int col = bn + wc * 32 + nt * 8 + (lane & 3) * 2;
            #pragma unroll
            for (int h = 0; h < 2; h++) {
                int r = r0 + h * 8;
                if (r >= M) continue;
                float v0 = c[mt][nt][h * 2 + 0];
                float v1 = c[mt][nt][h * 2 + 1];
                if constexpr (EPI == 1) {
                    v0 += bias[col];     v1 += bias[col + 1];
                    v0 = 0.5f * v0 * (1.f + erff(v0 * 0.70710678118654752f));
                    v1 = 0.5f * v1 * (1.f + erff(v1 * 0.70710678118654752f));
                } else if constexpr (EPI == 2) {
                    float2 rr = *(const float2*)(Rf + (long)r * ldc + col);
                    v0 += bias[col] + rr.x;  v1 += bias[col + 1] + rr.y;
                } else if constexpr (EPI == 3) {
                    float2 rr = *(const float2*)(Rf + (long)r * ldc + col);
                    v0 += rr.x;  v1 += rr.y;
                }
                if constexpr (OUT == 0) {
                    *(__half2*)(Ch + (long)r * ldc + col) = __floats2half2_rn(v0, v1);
                } else if constexpr (OUT == 1) {
                    *(float2*)(Cf + (long)r * ldc + col) = make_float2(v0, v1);
                } else {
                    *(float2*)(Cf + (long)r * ldc + col) = make_float2(v0, v1);
                    *(__half2*)(Ch + (long)r * ldc + col) = __floats2half2_rn(v0, v1);
                }
            }
        }
    }
}

// ============== small batched fp16 GEMM (KC + VC in one launch) =============
__global__ void __launch_bounds__(128)
hgemm_kv(const __half* __restrict__ Et, const __half* __restrict__ QKVS,
         __half* __restrict__ KC, __half* __restrict__ VC)
{
    constexpr int BK = 16, LDS_ = BK + 8;
    __shared__ __half As[2][64][LDS_];
    __shared__ __half Bs[2][64][LDS_];

    const int lda = ETLD, ldb = 3 * DIM_C, ldc = DH_C, K = ETLD;
    int e = blockIdx.z;
    bool isV = e >= BS_C * HEADS_C;
    int eb = isV ? e - BS_C * HEADS_C : e;
    int o = eb >> 3, ii = eb & 7;
    const __half* B = QKVS + (isV ? 2 * DIM_C : DIM_C) +
                      (long)o * ((long)NT_S * 3 * DIM_C) + ii * 64;
    __half* C = (isV ? VC : KC) + (long)eb * (KLIN_C * DH_C);
    const int bm = blockIdx.y * 64;
    const __half* A = Et + (long)bm * lda;

    const int tid = threadIdx.x, lane = tid & 31, warp = tid >> 5;
    const int wr = warp >> 1, wc = warp & 1;

    float c[2][4][4];
    #pragma unroll
    for (int i = 0; i < 2; i++)
        #pragma unroll
        for (int j = 0; j < 4; j++)
            #pragma unroll
            for (int q = 0; q < 4; q++) c[i][j][q] = 0.f;

    float4 a4, b4;
    auto loadg = [&](int t) {
        int k0 = t * BK;
        {
            int row = tid >> 1, seg = tid & 1;
            a4 = *(const float4*)(A + (long)row * lda + k0 + seg * 8);
        }
        {
            int kk = tid >> 3, nseg = tid & 7;
            b4 = *(const float4*)(B + (long)(t * BK + kk) * ldb + nseg * 8);
        }
    };
    auto stores = [&](int buf) {
        {
            int row = tid >> 1, seg = tid & 1;
            *(float4*)&As[buf][row][seg * 8] = a4;
        }
        {
            int kk = tid >> 3, nseg = tid & 7;
            const __half* hp = (const __half*)&b4;
            #pragma unroll
            for (int j = 0; j < 8; j++) Bs[buf][nseg * 8 + j][kk] = hp[j];
        }
    };
    auto comp = [&](int cu) {
        uint32_t af[2][4], bf[4][2];
        #pragma unroll
        for (int mt = 0; mt < 2; mt++) {
            uint32_t ad = smaddr(&As[cu][wr * 32 + mt * 16 + (lane & 15)]
                                    [((lane & 16) ? 8 : 0)]);
            ldmx4(af[mt][0], af[mt][1], af[mt][2], af[mt][3], ad);
        }
        #pragma unroll
        for (int p = 0; p < 2; p++) {
            int n0 = wc * 32 + p * 16;
            uint32_t bd = smaddr(&Bs[cu][n0 + (lane & 7) + ((lane & 16) ? 8 : 0)]
                                    [(lane & 8)]);
            uint32_t r0, r1, r2, r3;
            ldmx4(r0, r1, r2, r3, bd);
            bf[2 * p][0] = r0; bf[2 * p][1] = r1;
            bf[2 * p + 1][0] = r2; bf[2 * p + 1][1] = r3;
        }
        #pragma unroll
        for (int mt = 0; mt < 2; mt++)
            #pragma unroll
            for (int nt = 0; nt < 4; nt++)
                mma16816(c[mt][nt], af[mt], bf[nt]);
    };

    int ntl = K / BK;
    loadg(0);
    stores(0);
    __syncthreads();
    int cu = 0;
    for (int t = 0; t < ntl; t++) {
        if (t + 1 < ntl) loadg(t + 1);
        comp(cu);
        if (t + 1 < ntl) stores(cu ^ 1);
        __syncthreads();
        cu ^= 1;
    }

    #pragma unroll
    for (int mt = 0; mt < 2; mt++) {
        #pragma unroll
        for (int nt = 0; nt < 4; nt++) {
            int r0 = bm + wr * 32 + mt * 16 + (lane >> 2);
            int col = wc * 32 + nt * 8 + (lane & 3) * 2;
            #pragma unroll
            for (int h = 0; h < 2; h++) {
                int r = r0 + h * 8;
                if (col < DH_C) {
                    *(__half2*)(C + (long)r * ldc + col) =
                        __floats2half2_rn(c[mt][nt][h * 2], c[mt][nt][h * 2 + 1]);
                }
            }
        }
    }
}

extern "C" void kernel_launch(void* const* d_in, const int* in_sizes, int n_in,
                              void* d_out, int out_size) {
    const float* x      = (const float*)d_in[0];
    const float* Wqkv_t = (const float*)d_in[1];
    const float* Wo_t   = (const float*)d_in[2];
    const float* Wqkv_s = (const float*)d_in[3];
    const float* Wo_s   = (const float*)d_in[4];
    const float* E      = (const float*)d_in[5];
    const float* W1     = (const float*)d_in[6];
    const float* b1     = (const float*)d_in[7];
    const float* W2     = (const float*)d_in[8];
    const float* b2     = (const float*)d_in[9];
    float* out = (float*)d_out;

    __half *pXT, *pQKVT, *pOT, *pZ, *pQKVS, *pEt, *pKC, *pVC, *pOS, *pY2h, *pH;
    float  *pfXT, *pfY1, *pfZ, *pfY2;
    __half *ptWqkv_t, *ptWo_t, *ptWqkv_s, *ptWo_s, *ptW1, *ptW2;
    cudaGetSymbolAddress((void**)&pXT,   hXT);
    cudaGetSymbolAddress((void**)&pfXT,  fXT);
    cudaGetSymbolAddress((void**)&pQKVT, hQKVT);
    cudaGetSymbolAddress((void**)&pOT,   hOT);
    cudaGetSymbolAddress((void**)&pfY1,  fY1);
    cudaGetSymbolAddress((void**)&pZ,    hZ);
    cudaGetSymbolAddress((void**)&pfZ,   fZ);
    cudaGetSymbolAddress((void**)&pQKVS, hQKVS);
    cudaGetSymbolAddress((void**)&pEt,   hEt);
    cudaGetSymbolAddress((void**)&pKC,   hKC);
    cudaGetSymbolAddress((void**)&pVC,   hVC);
    cudaGetSymbolAddress((void**)&pOS,   hOS);
    cudaGetSymbolAddress((void**)&pfY2,  fY2);
    cudaGetSymbolAddress((void**)&pY2h,  hY2);
    cudaGetSymbolAddress((void**)&pH,    hH);
    cudaGetSymbolAddress((void**)&ptWqkv_t, tWqkv_t);
    cudaGetSymbolAddress((void**)&ptWo_t,   tWo_t);
    cudaGetSymbolAddress((void**)&ptWqkv_s, tWqkv_s);
    cudaGetSymbolAddress((void**)&ptWo_s,   tWo_s);
    cudaGetSymbolAddress((void**)&ptW1,     tW1);
    cudaGetSymbolAddress((void**)&ptW2,     tW2);

    cudaFuncSetAttribute(attn_t, cudaFuncAttributeMaxDynamicSharedMemorySize, ATNT_SMEM);
    cudaFuncSetAttribute(attn_s, cudaFuncAttributeMaxDynamicSharedMemorySize, ATNS_SMEM);
    cudaFuncSetAttribute(hgemm_big<0, 0>, cudaFuncAttributeMaxDynamicSharedMemorySize, HGB_SMEM);
    cudaFuncSetAttribute(hgemm_big<1, 0>, cudaFuncAttributeMaxDynamicSharedMemorySize, HGB_SMEM);
    cudaFuncSetAttribute(hgemm_big<2, 1>, cudaFuncAttributeMaxDynamicSharedMemorySize, HGB_SMEM);
    cudaFuncSetAttribute(hgemm_big<3, 1>, cudaFuncAttributeMaxDynamicSharedMemorySize, HGB_SMEM);
    cudaFuncSetAttribute(hgemm_big<3, 2>, cudaFuncAttributeMaxDynamicSharedMemorySize, HGB_SMEM);

    const int MT = BT_C * NT_T;   // 16448
    const int MS = BS_C * NT_S;   // 16640
    const int MT_T = (MT + 127) / 128;   // 129
    const int MS_T = (MS + 127) / 128;   // 130

    // 0. prep
    {
        long total = 786432L + 262144 + 786432 + 262144 + 524288 + 524288;
        prep_weights<<<(unsigned)((total + 255) / 256), 256>>>(
            Wqkv_t, Wo_t, Wqkv_s, Wo_s, W1, W2);
    }
    transpose_E<<<(KLIN_C * NT_S + 255) / 256, 256>>>(E);
    build_xt<<<(unsigned)(((long)BT_C * NT_T * DIM_C + 255) / 256), 256>>>(x);

    // temporal path
    hgemm_big<0, 0><<<dim3(12, MT_T), 256, HGB_SMEM>>>(
        pXT, ptWqkv_t, pQKVT, nullptr, nullptr, nullptr, MT, 3 * DIM_C, DIM_C, 3 * DIM_C);
    attn_t<<<dim3(5, BT_C * HEADS_C), 512, ATNT_SMEM>>>();
    hgemm_big<3, 1><<<dim3(4, MT_T), 256, HGB_SMEM>>>(
        pOT, ptWo_t, nullptr, pfY1, nullptr, pfXT, MT, DIM_C, DIM_C, DIM_C);

    // spatial path
    build_z<<<(unsigned)(((long)BS_C * NT_S * DIM_C + 255) / 256), 256>>>();
    hgemm_big<0, 0><<<dim3(12, MS_T), 256, HGB_SMEM>>>(
        pZ, ptWqkv_s, pQKVS, nullptr, nullptr, nullptr, MS, 3 * DIM_C, DIM_C, 3 * DIM_C);
    hgemm_kv<<<dim3(1, 2, 2 * BS_C * HEADS_C), 128>>>(pEt, pQKVS, pKC, pVC);
    attn_s<<<BS_C * HEADS_C, 320, ATNS_SMEM>>>();
    hgemm_big<3, 2><<<dim3(4, MS_T), 256, HGB_SMEM>>>(
        pOS, ptWo_s, pY2h, pfY2, nullptr, pfZ, MS, DIM_C, DIM_C, DIM_C);

    // FFN
    hgemm_big<1, 0><<<dim3(8, MS_T), 256, HGB_SMEM>>>(
        pY2h, ptW1, pH, nullptr, b1, nullptr, MS, DFF_C, DIM_C, DFF_C);
    hgemm_big<2, 1><<<dim3(4, MS_T), 256, HGB_SMEM>>>(
        pH, ptW2, nullptr, out, b2, pfY2, MS, DIM_C, DFF_C, DIM_C);
    (void)in_sizes; (void)n_in; (void)out_size;
}

// round 15
// speedup vs baseline: 1.0738x; 1.0738x over previous
#include <cuda_runtime.h>
#include <cuda_fp16.h>
#include <math.h>
#include <stdint.h>

// ---------------------------------------------------------------------------
// TimeSformer block, sm_103 legacy-mma path. Round 14:
//   * hgemm_big: back to R12 3-stage x 32-K (best measured: 823.3us)
//   * attn_t: V streamed in cp.async chunks during PV instead of resident ->
//     smem 125KB -> 105KB -> 2 CTAs/SM. Bit-identical MMA order.
//   * attn_s / rest unchanged.
// ---------------------------------------------------------------------------

#define FRAMES_C  256
#define PATCHES_C 64
#define DIM_C     512
#define HEADS_C   8
#define DH_C      64
#define DFF_C     1024
#define KLIN_C    128
#define NT_T      257
#define NT_S      65
#define BT_C      64
#define BS_C      256
#define ETLD      80
#define SFLD_T    276
#define SFLD_S    132

// ------------------------- scratch (device globals) ------------------------
__device__ __half hXT  [((size_t)BT_C * NT_T + 64) * DIM_C];
__device__ float  fXT  [(size_t)BT_C * NT_T * DIM_C];
__device__ __half hQKVT[((size_t)BT_C * NT_T + 16) * 3 * DIM_C];
__device__ __half hOT  [((size_t)BT_C * NT_T + 64) * DIM_C];
__device__ float  fY1  [(size_t)BT_C * NT_T * DIM_C];
__device__ __half hZ   [((size_t)BS_C * NT_S + 64) * DIM_C];
__device__ float  fZ   [(size_t)BS_C * NT_S * DIM_C];
__device__ __half hQKVS[((size_t)BS_C * NT_S + 16) * 3 * DIM_C];
__device__ __half hEt  [(size_t)KLIN_C * ETLD];
__device__ __half hKC  [(size_t)BS_C * HEADS_C * KLIN_C * DH_C];
__device__ __half hVC  [(size_t)BS_C * HEADS_C * KLIN_C * DH_C];
__device__ __half hOS  [((size_t)BS_C * NT_S + 64) * DIM_C];
__device__ float  fY2  [(size_t)BS_C * NT_S * DIM_C];
__device__ __half hY2  [((size_t)BS_C * NT_S + 64) * DIM_C];
__device__ __half hH   [((size_t)BS_C * NT_S + 64) * DFF_C];
__device__ __half tWqkv_t[(size_t)3 * DIM_C * DIM_C];
__device__ __half tWo_t  [(size_t)DIM_C * DIM_C];
__device__ __half tWqkv_s[(size_t)3 * DIM_C * DIM_C];
__device__ __half tWo_s  [(size_t)DIM_C * DIM_C];
__device__ __half tW1    [(size_t)DFF_C * DIM_C];
__device__ __half tW2    [(size_t)DIM_C * DFF_C];

// ------------------------------ helpers -------------------------------------
__device__ __forceinline__ uint32_t smaddr(const void* p) {
    uint32_t a;
    asm("{ .reg .u64 t; cvta.to.shared.u64 t, %1; cvt.u32.u64 %0, t; }" : "=r"(a) : "l"(p));
    return a;
}
__device__ __forceinline__ void ldmx4(uint32_t& r0, uint32_t& r1, uint32_t& r2, uint32_t& r3,
                                      uint32_t a) {
    asm volatile("ldmatrix.sync.aligned.m8n8.x4.shared.b16 {%0,%1,%2,%3}, [%4];"
                 : "=r"(r0), "=r"(r1), "=r"(r2), "=r"(r3) : "r"(a));
}
__device__ __forceinline__ void ldmx4t(uint32_t& r0, uint32_t& r1, uint32_t& r2, uint32_t& r3,
                                       uint32_t a) {
    asm volatile("ldmatrix.sync.aligned.m8n8.x4.trans.shared.b16 {%0,%1,%2,%3}, [%4];"
                 : "=r"(r0), "=r"(r1), "=r"(r2), "=r"(r3) : "r"(a));
}
__device__ __forceinline__ void mma16816(float c[4], const uint32_t a[4], const uint32_t b[2]) {
    asm volatile("mma.sync.aligned.m16n8k16.row.col.f32.f16.f16.f32 "
                 "{%0,%1,%2,%3},{%4,%5,%6,%7},{%8,%9},{%0,%1,%2,%3};"
                 : "+f"(c[0]), "+f"(c[1]), "+f"(c[2]), "+f"(c[3])
                 : "r"(a[0]), "r"(a[1]), "r"(a[2]), "r"(a[3]), "r"(b[0]), "r"(b[1]));
}
#define CPA16(dst, src) \
    asm volatile("cp.async.cg.shared.global [%0], [%1], 16;" :: "r"(dst), "l"(src) : "memory")
#define CPA_COMMIT() asm volatile("cp.async.commit_group;" ::: "memory")
#define CPA_WAIT(n)  asm volatile("cp.async.wait_group %0;" :: "n"(n) : "memory")

// ------------------------------- prep kernels -------------------------------
__global__ void prep_weights(const float* __restrict__ Wqkv_t, const float* __restrict__ Wo_t,
                             const float* __restrict__ Wqkv_s, const float* __restrict__ Wo_s,
                             const float* __restrict__ W1, const float* __restrict__ W2) {
    long i = (long)blockIdx.x * 256 + threadIdx.x;
    const long n1 = 786432, n2 = n1 + 262144, n3 = n2 + 786432,
               n4 = n3 + 262144, n5 = n4 + 524288, n6 = n5 + 524288;
    const float* src; __half* dst; long j; int K, N;
    if (i < n1)      { src = Wqkv_t; dst = tWqkv_t; j = i;      K = 512;  N = 1536; }
    else if (i < n2) { src = Wo_t;   dst = tWo_t;   j = i - n1; K = 512;  N = 512;  }
    else if (i < n3) { src = Wqkv_s; dst = tWqkv_s; j = i - n2; K = 512;  N = 1536; }
    else if (i < n4) { src = Wo_s;   dst = tWo_s;   j = i - n3; K = 512;  N = 512;  }
    else if (i < n5) { src = W1;     dst = tW1;     j = i - n4; K = 512;  N = 1024; }
    else if (i < n6) { src = W2;     dst = tW2;     j = i - n5; K = 1024; N = 512;  }
    else return;
    int k = (int)(j % K), n = (int)(j / K);
    dst[j] = __float2half_rn(src[(long)k * N + n]);
}
__global__ void build_xt(const float* __restrict__ x) {
    long idx = (long)blockIdx.x * blockDim.x + threadIdx.x;
    const long total = (long)BT_C * NT_T * DIM_C;
    if (idx >= total) return;
    int d = (int)(idx % DIM_C);
    long r = idx / DIM_C;
    int t = (int)(r % NT_T);
    int p = (int)(r / NT_T);
    float v;
    if (t == 0) v = x[d];
    else        v = x[(long)(1 + (t - 1) * PATCHES_C + p) * DIM_C + d];
    hXT[idx] = __float2half_rn(v);
    fXT[idx] = v;
}
__global__ void build_z() {
    long idx = (long)blockIdx.x * blockDim.x + threadIdx.x;
    const long total = (long)BS_C * NT_S * DIM_C;
    if (idx >= total) return;
    int d = (int)(idx % DIM_C);
    long r = idx / DIM_C;
    int s = (int)(r % NT_S);
    int f = (int)(r / NT_S);
    float v;
    if (s == 0) v = fY1[(long)(f & 63) * NT_T * DIM_C + d];
    else        v = fY1[(long)(s - 1) * NT_T * DIM_C + (long)(1 + f) * DIM_C + d];
    hZ[idx] = __float2half_rn(v);
    fZ[idx] = v;
}
__global__ void transpose_E(const float* __restrict__ E) {
    int i = blockIdx.x * blockDim.x + threadIdx.x;
    if (i >= KLIN_C * NT_S) return;
    int j = i % NT_S, kc = i / NT_S;
    hEt[kc * ETLD + j] = __float2half_rn(E[j * KLIN_C + kc]);
}

// ========= fused temporal attention (257 keys, dh=64), 512 threads ==========
// smem: Q[64][72]h | K[64][72]h | V2[2][64][72]h | SPf[64][276]f = 105KB
// V is streamed in 5 cp.async chunks during PV (pad-row content harmless:
// corresponding probs are zero). 2 CTAs/SM.
#define ATNT_SMEM (9216 + 9216 + 18432 + 64 * SFLD_T * 4)
__global__ void __launch_bounds__(512, 2)
attn_t() {
    extern __shared__ char sm[];
    __half* Qs = (__half*)sm;
    __half* Ks = (__half*)(sm + 9216);
    // V double buffers at sm+18432, sm+27648
    float*  SPf = (float*)(sm + 36864);
    const uint32_t sbase = smaddr(sm);
    const int tid = threadIdx.x, lane = tid & 31, warp = tid >> 5;
    const int bm = blockIdx.x * 64;
    const int b = blockIdx.y >> 3, h = blockIdx.y & 7;
    const __half* Qg = hQKVT + (size_t)b * NT_T * (3 * DIM_C) + h * 64;
    const __half* Kg = Qg + DIM_C;
    const __half* Vg = Qg + 2 * DIM_C;
    const float4 z4 = make_float4(0.f, 0.f, 0.f, 0.f);

    {   // Q 64x64
        int r = tid >> 3, s = tid & 7;
        int gr = bm + r;
        float4 v = (gr < NT_T) ? *(const float4*)(Qg + (size_t)gr * 1536 + s * 8) : z4;
        *(float4*)&Qs[r * 72 + s * 8] = v;
    }
    __syncthreads();

    const int wr = warp >> 2, wc = warp & 3;   // 4x4
    uint32_t aq[4][4];
    #pragma unroll
    for (int ks = 0; ks < 4; ks++) {
        uint32_t ad = smaddr(&Qs[(wr * 16 + (lane & 15)) * 72 +
                                 ks * 16 + ((lane & 16) ? 8 : 0)]);
        ldmx4(aq[ks][0], aq[ks][1], aq[ks][2], aq[ks][3], ad);
    }

    for (int kt = 0; kt < 5; kt++) {
        __syncthreads();
        {   // K tile 64x64
            int r = tid >> 3, s = tid & 7;
            int key = kt * 64 + r;
            float4 v = (key < NT_T) ? *(const float4*)(Kg + (size_t)key * 1536 + s * 8) : z4;
            *(float4*)&Ks[r * 72 + s * 8] = v;
        }
        __syncthreads();
        float c[2][4];
        #pragma unroll
        for (int nt = 0; nt < 2; nt++)
            #pragma unroll
            for (int q = 0; q < 4; q++) c[nt][q] = 0.f;
        #pragma unroll
        for (int ks = 0; ks < 4; ks++) {
            uint32_t r0, r1, r2, r3;
            uint32_t bd = smaddr(&Ks[(wc * 16 + (lane & 7) + ((lane & 16) ? 8 : 0)) * 72 +
                                     ks * 16 + (lane & 8)]);
            ldmx4(r0, r1, r2, r3, bd);
            uint32_t bf0[2] = {r0, r1}, bf1[2] = {r2, r3};
            mma16816(c[0], aq[ks], bf0);
            mma16816(c[1], aq[ks], bf1);
        }
        #pragma unroll
        for (int nt = 0; nt < 2; nt++) {
            int row = wr * 16 + (lane >> 2);
            int col0 = kt * 64 + wc * 16 + nt * 8 + (lane & 3) * 2;
            #pragma unroll
            for (int h2 = 0; h2 < 2; h2++)
                #pragma unroll
                for (int j = 0; j < 2; j++) {
                    int col = col0 + j;
                    if (col < NT_T)
                        SPf[(row + h2 * 8) * SFLD_T + col] =
                            c[nt][h2 * 2 + j] * 0.125f;
                }
        }
    }
    __syncthreads();

    // softmax (fp32), probs -> half in-place
    #pragma unroll 1
    for (int rr = 0; rr < 4; rr++) {
        int row = warp * 4 + rr;
        float* sp = &SPf[row * SFLD_T];
        __half* hp = (__half*)sp;
        float v[9];
        float m = -1e30f;
        #pragma unroll
        for (int i2 = 0; i2 < 9; i2++) {
            int cc = lane + i2 * 32;
            v[i2] = (cc < NT_T) ? sp[cc] : -1e30f;
            m = fmaxf(m, v[i2]);
        }
        #pragma unroll
        for (int s = 16; s > 0; s >>= 1) m = fmaxf(m, __shfl_xor_sync(0xffffffffu, m, s));
        float sum = 0.f;
        #pragma unroll
        for (int i2 = 0; i2 < 9; i2++) {
            int cc = lane + i2 * 32;
            if (cc < NT_T) { v[i2] = __expf(v[i2] - m); sum += v[i2]; }
        }
        #pragma unroll
        for (int s = 16; s > 0; s >>= 1) sum += __shfl_xor_sync(0xffffffffu, sum, s);
        float inv = 1.f / sum;
        __syncwarp();
        #pragma unroll
        for (int i2 = 0; i2 < 9; i2++) {
            int cc = lane + i2 * 32;
            if (cc < NT_T) hp[cc] = __float2half_rn(v[i2] * inv);
        }
        for (int cc = NT_T + lane; cc < 272; cc += 32) hp[cc] = __float2half_rn(0.f);
    }
    __syncthreads();

    // PV with streamed V chunks (5 chunks: 64,64,64,64,16 rows)
    auto pvpre = [&](int chunk) {
        int rows = (chunk == 4) ? 16 : 64;
        uint32_t vb = sbase + 18432 + (chunk & 1) * 9216;
        if (tid < rows * 8) {
            int r = tid >> 3, s = tid & 7;
            // rows beyond NT_T read in-bounds finite data (hQKVT +16 pad rows);
            // their probs are zero so the product contributes nothing.
            CPA16(vb + r * 144 + s * 16,
                  Vg + (size_t)(chunk * 64 + r) * 1536 + s * 8);
        }
        CPA_COMMIT();
    };

    float o[2][4];
    #pragma unroll
    for (int nt = 0; nt < 2; nt++)
        #pragma unroll
        for (int q = 0; q < 4; q++) o[nt][q] = 0.f;
    __half* Ph = (__half*)SPf;
    const int PLD = SFLD_T * 2;

    pvpre(0);
    #pragma unroll 1
    for (int chunk = 0; chunk < 5; chunk++) {
        if (chunk + 1 < 5) { pvpre(chunk + 1); CPA_WAIT(1); }
        else               { CPA_WAIT(0); }
        __syncthreads();
        const __half* Vb = (const __half*)(sm + 18432 + (chunk & 1) * 9216);
        int ks_end = (chunk == 4) ? 1 : 4;
        #pragma unroll 1
        for (int kss = 0; kss < ks_end; kss++) {
            int ks = chunk * 4 + kss;
            uint32_t ap[4];
            uint32_t ad = smaddr(&Ph[(wr * 16 + (lane & 15)) * PLD +
                                     ks * 16 + ((lane & 16) ? 8 : 0)]);
            ldmx4(ap[0], ap[1], ap[2], ap[3], ad);
            uint32_t r0, r1, r2, r3;
            uint32_t bd = smaddr(&Vb[(kss * 16 + (lane & 15)) * 72 +
                                     wc * 16 + ((lane & 16) ? 8 : 0)]);
            ldmx4t(r0, r1, r2, r3, bd);
            uint32_t bf0[2] = {r0, r1}, bf1[2] = {r2, r3};
            mma16816(o[0], ap, bf0);
            mma16816(o[1], ap, bf1);
        }
        __syncthreads();
    }

    #pragma unroll
    for (int nt = 0; nt < 2; nt++) {
        int row0 = bm + wr * 16 + (lane >> 2);
        int col0 = h * 64 + wc * 16 + nt * 8 + (lane & 3) * 2;
        #pragma unroll
        for (int h2 = 0; h2 < 2; h2++) {
            int row = row0 + h2 * 8;
            if (row >= NT_T) continue;
            #pragma unroll
            for (int j = 0; j < 2; j++)
                hOT[((size_t)b * NT_T + row) * 512 + col0 + j] =
                    __float2half_rn(o[nt][h2 * 2 + j]);
        }
    }
}

// ===== fused spatial Linformer attention (128 keys), 320 threads ============
#define ATNS_SMEM (11520 + 18432 + 18432 + 80 * SFLD_S * 4)
__global__ void __launch_bounds__(320, 2)
attn_s() {
    extern __shared__ char sm[];
    __half* Qs = (__half*)sm;
    __half* Ks = (__half*)(sm + 11520);
    __half* Vs = (__half*)(sm + 29952);
    float*  SPf = (float*)(sm + 48384);
    const int tid = threadIdx.x, lane = tid & 31, warp = tid >> 5;
    const int f = blockIdx.x >> 3, h = blockIdx.x & 7;
    const __half* Qg = hQKVS + (size_t)f * NT_S * (3 * DIM_C) + h * 64;
    const __half* Kc = hKC + (size_t)blockIdx.x * (KLIN_C * DH_C);
    const __half* Vc = hVC + (size_t)blockIdx.x * (KLIN_C * DH_C);
    const float4 z4 = make_float4(0.f, 0.f, 0.f, 0.f);

    for (int i = tid; i < 640; i += 320) {
        int r = i >> 3, s = i & 7;
        float4 v = (r < NT_S) ? *(const float4*)(Qg + (size_t)r * 1536 + s * 8) : z4;
        *(float4*)&Qs[r * 72 + s * 8] = v;
    }
    for (int i = tid; i < 1024; i += 320) {
        int r = i >> 3, s = i & 7;
        *(float4*)&Ks[r * 72 + s * 8] = *(const float4*)(Kc + (size_t)r * 64 + s * 8);
    }
    for (int i = tid; i < 1024; i += 320) {
        int r = i >> 3, s = i & 7;
        *(float4*)&Vs[r * 72 + s * 8] = *(const float4*)(Vc + (size_t)r * 64 + s * 8);
    }
    __syncthreads();

    const int wr = warp >> 1, wc = warp & 1;
    uint32_t aq[4][4];
    #pragma unroll
    for (int ks = 0; ks < 4; ks++) {
        uint32_t ad = smaddr(&Qs[(wr * 16 + (lane & 15)) * 72 +
                                 ks * 16 + ((lane & 16) ? 8 : 0)]);
        ldmx4(aq[ks][0], aq[ks][1], aq[ks][2], aq[ks][3], ad);
    }
    float c[8][4];
    #pragma unroll
    for (int nt = 0; nt < 8; nt++)
        #pragma unroll
        for (int q = 0; q < 4; q++) c[nt][q] = 0.f;
    #pragma unroll
    for (int ks = 0; ks < 4; ks++)
        #pragma unroll
        for (int p = 0; p < 4; p++) {
            uint32_t r0, r1, r2, r3;
            uint32_t bd = smaddr(&Ks[(wc * 64 + p * 16 + (lane & 7) +
                                      ((lane & 16) ? 8 : 0)) * 72 +
                                     ks * 16 + (lane & 8)]);
            ldmx4(r0, r1, r2, r3, bd);
            uint32_t bf0[2] = {r0, r1}, bf1[2] = {r2, r3};
            mma16816(c[2 * p], aq[ks], bf0);
            mma16816(c[2 * p + 1], aq[ks], bf1);
        }
    #pragma unroll
    for (int nt = 0; nt < 8; nt++) {
        int row = wr * 16 + (lane >> 2);
        int col0 = wc * 64 + (nt >> 1) * 16 + (nt & 1) * 8 + (lane & 3) * 2;
        #pragma unroll
        for (int h2 = 0; h2 < 2; h2++)
            #pragma unroll
            for (int j = 0; j < 2; j++)
                SPf[(row + h2 * 8) * SFLD_S + col0 + j] =
                    c[nt][h2 * 2 + j] * 0.125f;
    }
    __syncthreads();

    #pragma unroll 1
    for (int rr = 0; rr < 8; rr++) {
        int row = warp * 8 + rr;
        float* sp = &SPf[row * SFLD_S];
        __half* hp = (__half*)sp;
        if (row < NT_S) {
            float v[4];
            float m = -1e30f;
            #pragma unroll
            for (int i2 = 0; i2 < 4; i2++) {
                v[i2] = sp[lane + i2 * 32];
                m = fmaxf(m, v[i2]);
            }
            #pragma unroll
            for (int s = 16; s > 0; s >>= 1) m = fmaxf(m, __shfl_xor_sync(0xffffffffu, m, s));
            float sum = 0.f;
            #pragma unroll
            for (int i2 = 0; i2 < 4; i2++) { v[i2] = __expf(v[i2] - m); sum += v[i2]; }
            #pragma unroll
            for (int s = 16; s > 0; s >>= 1) sum += __shfl_xor_sync(0xffffffffu, sum, s);
            float inv = 1.f / sum;
            __syncwarp();
            #pragma unroll
            for (int i2 = 0; i2 < 4; i2++)
                hp[lane + i2 * 32] = __float2half_rn(v[i2] * inv);
        } else {
            #pragma unroll
            for (int i2 = 0; i2 < 4; i2++) hp[lane + i2 * 32] = __float2half_rn(0.f);
        }
    }
    __syncthreads();

    float o[4][4];
    #pragma unroll
    for (int nt = 0; nt < 4; nt++)
        #pragma unroll
        for (int q = 0; q < 4; q++) o[nt][q] = 0.f;
    __half* Ph = (__half*)SPf;
    const int PLD = SFLD_S * 2;
    #pragma unroll 1
    for (int ks = 0; ks < 8; ks++) {
        uint32_t ap[4];
        uint32_t ad = smaddr(&Ph[(wr * 16 + (lane & 15)) * PLD +
                                 ks * 16 + ((lane & 16) ? 8 : 0)]);
        ldmx4(ap[0], ap[1], ap[2], ap[3], ad);
        #pragma unroll
        for (int p = 0; p < 2; p++) {
            uint32_t r0, r1, r2, r3;
            uint32_t bd = smaddr(&Vs[(ks * 16 + (lane & 15)) * 72 +
                                     wc * 32 + p * 16 + ((lane & 16) ? 8 : 0)]);
            ldmx4t(r0, r1, r2, r3, bd);
            uint32_t bf0[2] = {r0, r1}, bf1[2] = {r2, r3};
            mma16816(o[2 * p], ap, bf0);
            mma16816(o[2 * p + 1], ap, bf1);
        }
    }
    #pragma unroll
    for (int nt = 0; nt < 4; nt++) {
        int row0 = wr * 16 + (lane >> 2);
        int col0 = h * 64 + wc * 32 + (nt >> 1) * 16 + (nt & 1) * 8 + (lane & 3) * 2;
        #pragma unroll
        for (int h2 = 0; h2 < 2; h2++) {
            int row = row0 + h2 * 8;
            if (row >= NT_S) continue;
            #pragma unroll
            for (int j = 0; j < 2; j++)
                hOS[((size_t)f * NT_S + row) * 512 + col0 + j] =
                    __float2half_rn(o[nt][h2 * 2 + j]);
        }
    }
}

// ====== big fp16 GEMM, 3-stage x 32-K cp.async (R12 config, best known) =====
#define HGB_STAGE 20480
#define HGB_SMEM  (3 * HGB_STAGE)

template<int EPI, int OUT>
__global__ void __launch_bounds__(256, 2)
hgemm_big(const __half* __restrict__ A, const __half* __restrict__ Bt,
          __half* __restrict__ Ch, float* __restrict__ Cf,
          const float* __restrict__ bias, const float* __restrict__ Rf,
          int M, int N, int K, int ldc)
{
    constexpr int BK = 32;
    extern __shared__ char smraw[];
    const uint32_t sb = smaddr(smraw);

    const int tid = threadIdx.x, lane = tid & 31, warp = tid >> 5;
    const int wr = warp >> 2, wc = warp & 3;
    const int bm = blockIdx.y * 128, bn = blockIdx.x * 128;
    A  += (long)bm * K;
    Bt += (long)bn * K;

    float c[4][4][4];
    #pragma unroll
    for (int i = 0; i < 4; i++)
        #pragma unroll
        for (int j = 0; j < 4; j++)
            #pragma unroll
            for (int q = 0; q < 4; q++) c[i][j][q] = 0.f;

    auto prefetch = [&](int t) {
        int s = t - (t / 3) * 3;
        uint32_t ab = sb + s * HGB_STAGE;
        uint32_t bb = ab + 10240;
        int k0 = t * BK;
        #pragma unroll
        for (int i = 0; i < 2; i++) {
            int ch = tid + i * 256;
            int row = ch >> 2, seg = ch & 3;
            CPA16(ab + row * 80 + seg * 16, A + (long)row * K + k0 + seg * 8);
            CPA16(bb + row * 80 + seg * 16, Bt + (long)row * K + k0 + seg * 8);
        }
        CPA_COMMIT();
    };

    auto comp = [&](int s) {
        const __half* Asb = (const __half*)(smraw + s * HGB_STAGE);
        const __half* Bsb = (const __half*)(smraw + s * HGB_STAGE + 10240);
        #pragma unroll
        for (int ks = 0; ks < 2; ks++) {
            int k0 = ks * 16;
            uint32_t af[4][4], bf[4][2];
            #pragma unroll
            for (int mt = 0; mt < 4; mt++) {
                uint32_t ad = smaddr(Asb + (wr * 64 + mt * 16 + (lane & 15)) * 40 +
                                     k0 + ((lane & 16) ? 8 : 0));
                ldmx4(af[mt][0], af[mt][1], af[mt][2], af[mt][3], ad);
            }
            #pragma unroll
            for (int p = 0; p < 2; p++) {
                int n0 = wc * 32 + p * 16;
                uint32_t bd = smaddr(Bsb + (n0 + (lane & 7) + ((lane & 16) ? 8 : 0)) * 40 +
                                     k0 + (lane & 8));
                uint32_t r0, r1, r2, r3;
                ldmx4(r0, r1, r2, r3, bd);
                bf[2 * p][0] = r0; bf[2 * p][1] = r1;
                bf[2 * p + 1][0] = r2; bf[2 * p + 1][1] = r3;
            }
            #pragma unroll
            for (int mt = 0; mt < 4; mt++)
                #pragma unroll
                for (int nt = 0; nt < 4; nt++)
                    mma16816(c[mt][nt], af[mt], bf[nt]);
        }
    };

    const int ntl = K / BK;
    prefetch(0);
    prefetch(1);
    CPA_WAIT(1);
    __syncthreads();
    int s = 0;
    for (int t = 0; t < ntl; t++) {
        comp(s);
        if (t + 2 < ntl) { prefetch(t + 2); CPA_WAIT(1); }
        else             { CPA_WAIT(0); }
        __syncthreads();
        s = (s == 2) ? 0 : s + 1;
    }

    #pragma unroll
    for (int mt = 0; mt < 4; mt++) {
        #pragma unroll
        for (int nt = 0; nt < 4; nt++) {
            int r0 = bm + wr * 64 + mt * 16 + (lane >> 2);
            int col = bn + wc * 32 + nt * 8 + (lane & 3) * 2;
            #pragma unroll
            for (int h = 0; h < 2; h++) {
                int r = r0 + h * 8;
                if (r >= M) continue;
                float v0 = c[mt][nt][h * 2 + 0];
                float v1 = c[mt][nt][h * 2 + 1];
                if constexpr (EPI == 1) {
                    v0 += bias[col];     v1 += bias[col + 1];
                    v0 = 0.5f * v0 * (1.f + erff(v0 * 0.70710678118654752f));
                    v1 = 0.5f * v1 * (1.f + erff(v1 * 0.70710678118654752f));
                } else if constexpr (EPI == 2) {
                    float2 rr = *(const float2*)(Rf + (long)r * ldc + col);
                    v0 += bias[col] + rr.x;  v1 += bias[col + 1] + rr.y;
                } else if constexpr (EPI == 3) {
                    float2 rr = *(const float2*)(Rf + (long)r * ldc + col);
                    v0 += rr.x;  v1 += rr.y;
                }
                if constexpr (OUT == 0) {
                    *(__half2*)(Ch + (long)r * ldc + col) = __floats2half2_rn(v0, v1);
                } else if constexpr (OUT == 1) {
                    *(float2*)(Cf + (long)r * ldc + col) = make_float2(v0, v1);
                } else {
                    *(float2*)(Cf + (long)r * ldc + col) = make_float2(v0, v1);
                    *(__half2*)(Ch + (long)r * ldc + col) = __floats2half2_rn(v0, v1);
                }
            }
        }
    }
}

// ============== small batched fp16 GEMM (KC + VC in one launch) =============
__global__ void __launch_bounds__(128)
hgemm_kv(const __half* __restrict__ Et, const __half* __restrict__ QKVS,
         __half* __restrict__ KC, __half* __restrict__ VC)
{
    constexpr int BK = 16, LDS_ = BK + 8;
    __shared__ __half As[2][64][LDS_];
    __shared__ __half Bs[2][64][LDS_];

    const int lda = ETLD, ldb = 3 * DIM_C, ldc = DH_C, K = ETLD;
    int e = blockIdx.z;
    bool isV = e >= BS_C * HEADS_C;
    int eb = isV ? e - BS_C * HEADS_C : e;
    int o = eb >> 3, ii = eb & 7;
    const __half* B = QKVS + (isV ? 2 * DIM_C : DIM_C) +
                      (long)o * ((long)NT_S * 3 * DIM_C) + ii * 64;
    __half* C = (isV ? VC : KC) + (long)eb * (KLIN_C * DH_C);
    const int bm = blockIdx.y * 64;
    const __half* A = Et + (long)bm * lda;

    const int tid = threadIdx.x, lane = tid & 31, warp = tid >> 5;
    const int wr = warp >> 1, wc = warp & 1;

    float c[2][4][4];
    #pragma unroll
    for (int i = 0; i < 2; i++)
        #pragma unroll
        for (int j = 0; j < 4; j++)
            #pragma unroll
            for (int q = 0; q < 4; q++) c[i][j][q] = 0.f;

    float4 a4, b4;
    auto loadg = [&](int t) {
        int k0 = t * BK;
        {
            int row = tid >> 1, seg = tid & 1;
            a4 = *(const float4*)(A + (long)row * lda + k0 + seg * 8);
        }
        {
            int kk = tid >> 3, nseg = tid & 7;
            b4 = *(const float4*)(B + (long)(t * BK + kk) * ldb + nseg * 8);
        }
    };
    auto stores = [&](int buf) {
        {
            int row = tid >> 1, seg = tid & 1;
            *(float4*)&As[buf][row][seg * 8] = a4;
        }
        {
            int kk = tid >> 3, nseg = tid & 7;
            const __half* hp = (const __half*)&b4;
            #pragma unroll
            for (int j = 0; j < 8; j++) Bs[buf][nseg * 8 + j][kk] = hp[j];
        }
    };
    auto comp = [&](int cu) {
        uint32_t af[2][4], bf[4][2];
        #pragma unroll
        for (int mt = 0; mt < 2; mt++) {
            uint32_t ad = smaddr(&As[cu][wr * 32 + mt * 16 + (lane & 15)]
                                    [((lane & 16) ? 8 : 0)]);
            ldmx4(af[mt][0], af[mt][1], af[mt][2], af[mt][3], ad);
        }
        #pragma unroll
        for (int p = 0; p < 2; p++) {
            int n0 = wc * 32 + p * 16;
            uint32_t bd = smaddr(&Bs[cu][n0 + (lane & 7) + ((lane & 16) ? 8 : 0)]
                                    [(lane & 8)]);
            uint32_t r0, r1, r2, r3;
            ldmx4(r0, r1, r2, r3, bd);
            bf[2 * p][0] = r0; bf[2 * p][1] = r1;
            bf[2 * p + 1][0] = r2; bf[2 * p + 1][1] = r3;
        }
        #pragma unroll
        for (int mt = 0; mt < 2; mt++)
            #pragma unroll
            for (int nt = 0; nt < 4; nt++)
                mma16816(c[mt][nt], af[mt], bf[nt]);
    };

    int ntl = K / BK;
    loadg(0);
    stores(0);
    __syncthreads();
    int cu = 0;
    for (int t = 0; t < ntl; t++) {
        if (t + 1 < ntl) loadg(t + 1);
        comp(cu);
        if (t + 1 < ntl) stores(cu ^ 1);
        __syncthreads();
        cu ^= 1;
    }

    #pragma unroll
    for (int mt = 0; mt < 2; mt++) {
        #pragma unroll
        for (int nt = 0; nt < 4; nt++) {
            int r0 = bm + wr * 32 + mt * 16 + (lane >> 2);
            int col = wc * 32 + nt * 8 + (lane & 3) * 2;
            #pragma unroll
            for (int h = 0; h < 2; h++) {
                int r = r0 + h * 8;
                if (col < DH_C) {
                    *(__half2*)(C + (long)r * ldc + col) =
                        __floats2half2_rn(c[mt][nt][h * 2], c[mt][nt][h * 2 + 1]);
                }
            }
        }
    }
}

extern "C" void kernel_launch(void* const* d_in, const int* in_sizes, int n_in,
                              void* d_out, int out_size) {
    const float* x      = (const float*)d_in[0];
    const float* Wqkv_t = (const float*)d_in[1];
    const float* Wo_t   = (const float*)d_in[2];
    const float* Wqkv_s = (const float*)d_in[3];
    const float* Wo_s   = (const float*)d_in[4];
    const float* E      = (const float*)d_in[5];
    const float* W1     = (const float*)d_in[6];
    const float* b1     = (const float*)d_in[7];
    const float* W2     = (const float*)d_in[8];
    const float* b2     = (const float*)d_in[9];
    float* out = (float*)d_out;

    __half *pXT, *pQKVT, *pOT, *pZ, *pQKVS, *pEt, *pKC, *pVC, *pOS, *pY2h, *pH;
    float  *pfXT, *pfY1, *pfZ, *pfY2;
    __half *ptWqkv_t, *ptWo_t, *ptWqkv_s, *ptWo_s, *ptW1, *ptW2;
    cudaGetSymbolAddress((void**)&pXT,   hXT);
    cudaGetSymbolAddress((void**)&pfXT,  fXT);
    cudaGetSymbolAddress((void**)&pQKVT, hQKVT);
    cudaGetSymbolAddress((void**)&pOT,   hOT);
    cudaGetSymbolAddress((void**)&pfY1,  fY1);
    cudaGetSymbolAddress((void**)&pZ,    hZ);
    cudaGetSymbolAddress((void**)&pfZ,   fZ);
    cudaGetSymbolAddress((void**)&pQKVS, hQKVS);
    cudaGetSymbolAddress((void**)&pEt,   hEt);
    cudaGetSymbolAddress((void**)&pKC,   hKC);
    cudaGetSymbolAddress((void**)&pVC,   hVC);
    cudaGetSymbolAddress((void**)&pOS,   hOS);
    cudaGetSymbolAddress((void**)&pfY2,  fY2);
    cudaGetSymbolAddress((void**)&pY2h,  hY2);
    cudaGetSymbolAddress((void**)&pH,    hH);
    cudaGetSymbolAddress((void**)&ptWqkv_t, tWqkv_t);
    cudaGetSymbolAddress((void**)&ptWo_t,   tWo_t);
    cudaGetSymbolAddress((void**)&ptWqkv_s, tWqkv_s);
    cudaGetSymbolAddress((void**)&ptWo_s,   tWo_s);
    cudaGetSymbolAddress((void**)&ptW1,     tW1);
    cudaGetSymbolAddress((void**)&ptW2,     tW2);

    cudaFuncSetAttribute(attn_t, cudaFuncAttributeMaxDynamicSharedMemorySize, ATNT_SMEM);
    cudaFuncSetAttribute(attn_s, cudaFuncAttributeMaxDynamicSharedMemorySize, ATNS_SMEM);
    cudaFuncSetAttribute(hgemm_big<0, 0>, cudaFuncAttributeMaxDynamicSharedMemorySize, HGB_SMEM);
    cudaFuncSetAttribute(hgemm_big<1, 0>, cudaFuncAttributeMaxDynamicSharedMemorySize, HGB_SMEM);
    cudaFuncSetAttribute(hgemm_big<2, 1>, cudaFuncAttributeMaxDynamicSharedMemorySize, HGB_SMEM);
    cudaFuncSetAttribute(hgemm_big<3, 1>, cudaFuncAttributeMaxDynamicSharedMemorySize, HGB_SMEM);
    cudaFuncSetAttribute(hgemm_big<3, 2>, cudaFuncAttributeMaxDynamicSharedMemorySize, HGB_SMEM);

    const int MT = BT_C * NT_T;   // 16448
    const int MS = BS_C * NT_S;   // 16640
    const int MT_T = (MT + 127) / 128;   // 129
    const int MS_T = (MS + 127) / 128;   // 130

    // 0. prep
    {
        long total = 786432L + 262144 + 786432 + 262144 + 524288 + 524288;
        prep_weights<<<(unsigned)((total + 255) / 256), 256>>>(
            Wqkv_t, Wo_t, Wqkv_s, Wo_s, W1, W2);
    }
    transpose_E<<<(KLIN_C * NT_S + 255) / 256, 256>>>(E);
    build_xt<<<(unsigned)(((long)BT_C * NT_T * DIM_C + 255) / 256), 256>>>(x);

    // temporal path
    hgemm_big<0, 0><<<dim3(12, MT_T), 256, HGB_SMEM>>>(
        pXT, ptWqkv_t, pQKVT, nullptr, nullptr, nullptr, MT, 3 * DIM_C, DIM_C, 3 * DIM_C);
    attn_t<<<dim3(5, BT_C * HEADS_C), 512, ATNT_SMEM>>>();
    hgemm_big<3, 1><<<dim3(4, MT_T), 256, HGB_SMEM>>>(
        pOT, ptWo_t, nullptr, pfY1, nullptr, pfXT, MT, DIM_C, DIM_C, DIM_C);

    // spatial path
    build_z<<<(unsigned)(((long)BS_C * NT_S * DIM_C + 255) / 256), 256>>>();
    hgemm_big<0, 0><<<dim3(12, MS_T), 256, HGB_SMEM>>>(
        pZ, ptWqkv_s, pQKVS, nullptr, nullptr, nullptr, MS, 3 * DIM_C, DIM_C, 3 * DIM_C);
    hgemm_kv<<<dim3(1, 2, 2 * BS_C * HEADS_C), 128>>>(pEt, pQKVS, pKC, pVC);
    attn_s<<<BS_C * HEADS_C, 320, ATNS_SMEM>>>();
    hgemm_big<3, 2><<<dim3(4, MS_T), 256, HGB_SMEM>>>(
        pOS, ptWo_s, pY2h, pfY2, nullptr, pfZ, MS, DIM_C, DIM_C, DIM_C);

    // FFN
    hgemm_big<1, 0><<<dim3(8, MS_T), 256, HGB_SMEM>>>(
        pY2h, ptW1, pH, nullptr, b1, nullptr, MS, DFF_C, DIM_C, DFF_C);
    hgemm_big<2, 1><<<dim3(4, MS_T), 256, HGB_SMEM>>>(
        pH, ptW2, nullptr, out, b2, pfY2, MS, DIM_C, DFF_C, DIM_C);
    (void)in_sizes; (void)n_in; (void)out_size;
}